// round 14
// baseline (speedup 1.0000x reference)
#include <cuda_runtime.h>
#include <math.h>
#include <stdint.h>

#define D      512
#define B      256
#define FOURD  2048
#define QS     1024   // 2*D
#define SPLITS 8
#define NW     8      // warps per attn block (256 threads)

// tensor-core GEMM tiling
#define GBM 64
#define GBN 64
#define GBK 16
#define KSPL 2
#define KCHUNK (QS / KSPL)    // 512
#define GNIT (KCHUNK / GBK)   // 32
#define SROW 18               // smem row stride in float2 (bank-conflict-free)

// ---- scratch (no allocations allowed) ----
__device__ float2 g_W2[FOURD * QS];     // Wcomb pre-split tf32 {hi,lo}, 16.8 MB
__device__ float2 g_q2[B * QS];         // qstar pre-split tf32 {hi,lo}
__device__ float  g_bsum[FOURD];
__device__ float  g_qstar[B * QS];      // [h | r] plain fp32 (attention/proj consumer)
__device__ float  g_c[B * D];
__device__ float  g_gpart[KSPL][B * FOURD];
__device__ int    g_segoff[B + 1];
// split-attention partials
__device__ float g_pm[B * SPLITS];
__device__ float g_pd[B * SPLITS];
__device__ float g_pr[B * SPLITS * D];

__device__ __forceinline__ float sigf(float v) { return 1.0f / (1.0f + expf(-v)); }

__device__ __forceinline__ void cp_async16(uint32_t dst_smem, const void* src) {
    asm volatile("cp.async.cg.shared.global [%0], [%1], 16;" :: "r"(dst_smem), "l"(src));
}

__device__ __forceinline__ uint32_t f2tf32(float x) {
    uint32_t r; asm("cvt.rna.tf32.f32 %0, %1;" : "=r"(r) : "f"(x)); return r;
}

__device__ __forceinline__ float2 tf32split(float v) {
    uint32_t h = f2tf32(v);
    float hf = __uint_as_float(h);
    uint32_t l = f2tf32(v - hf);
    return make_float2(hf, __uint_as_float(l));
}

__device__ __forceinline__ void mma_tf32(float* c, const uint32_t* a, const uint32_t* b) {
    asm volatile(
        "mma.sync.aligned.m16n8k8.row.col.f32.tf32.tf32.f32 "
        "{%0,%1,%2,%3}, {%4,%5,%6,%7}, {%8,%9}, {%0,%1,%2,%3};\n"
        : "+f"(c[0]), "+f"(c[1]), "+f"(c[2]), "+f"(c[3])
        : "r"(a[0]), "r"(a[1]), "r"(a[2]), "r"(a[3]), "r"(b[0]), "r"(b[1]));
}

// ---------------- fused init: Wcomb split + bsum + step0 + segscan ----------------
#define WCOMB_BLKS (FOURD * QS / 4 / 256)   // 2048
#define STEP0_BLKS (B * D / 256)            // 512
__global__ void k_init(const void* __restrict__ raw, int N,
                       const float* __restrict__ W_ih, const float* __restrict__ W_hh,
                       const float* __restrict__ b_ih, const float* __restrict__ b_hh) {
    int blk = blockIdx.x;
    int t = threadIdx.x;
    if (blk < WCOMB_BLKS) {
        int i4 = blk * 256 + t;
        float4 v = ((const float4*)W_ih)[i4];
        int idx = i4 * 4;
        int k = idx & (QS - 1);
        int n = idx >> 10;
        if (k < D) {
            float4 w = *(const float4*)(W_hh + n * D + k);
            v.x += w.x; v.y += w.y; v.z += w.z; v.w += w.w;
        }
        g_W2[idx + 0] = tf32split(v.x);
        g_W2[idx + 1] = tf32split(v.y);
        g_W2[idx + 2] = tf32split(v.z);
        g_W2[idx + 3] = tf32split(v.w);
        if (i4 < FOURD) g_bsum[i4] = b_ih[i4] + b_hh[i4];
    } else if (blk < WCOMB_BLKS + STEP0_BLKS) {
        int idx = (blk - WCOMB_BLKS) * 256 + t;
        int j = idx & (D - 1);
        float gi = b_ih[j]         + b_hh[j];
        float gg = b_ih[2 * D + j] + b_hh[2 * D + j];
        float go = b_ih[3 * D + j] + b_hh[3 * D + j];
        float c  = sigf(gi) * tanhf(gg);
        float h  = sigf(go) * tanhf(c);
        int b = idx >> 9;
        g_c[idx] = c;
        g_qstar[b * QS + j] = h;
        g_q2[b * QS + j] = tf32split(h);
    } else {
        const int* p32 = (const int*)raw;
        bool is64 = (p32[N - 1] == 0) || (p32[N - 2] == 0);
        int i = (blk - WCOMB_BLKS - STEP0_BLKS) * 256 + t;
        if (i >= N) return;
        int cur = is64 ? (int)((const long long*)raw)[i] : p32[i];
        if (i == 0) {
            for (int j = 0; j <= cur; j++) g_segoff[j] = 0;
        } else {
            int prev = is64 ? (int)((const long long*)raw)[i - 1] : p32[i - 1];
            for (int j = prev + 1; j <= cur; j++) g_segoff[j] = i;
        }
        if (i == N - 1) {
            for (int j = cur + 1; j <= B; j++) g_segoff[j] = N;
        }
    }
}

// ---------------- LSTM elementwise, float4, 128-thr blocks (sums 2 K-split partials) ----------------
__global__ void __launch_bounds__(128) k_lstm_ew() {
    int idx = blockIdx.x * 128 + threadIdx.x;   // over B*D/4
    if (idx >= B * D / 4) return;
    int b = idx >> 7;
    int j = (idx & 127) * 4;
    float4 gi = *(const float4*)&g_bsum[j];
    float4 gf = *(const float4*)&g_bsum[D + j];
    float4 gg = *(const float4*)&g_bsum[2 * D + j];
    float4 go = *(const float4*)&g_bsum[3 * D + j];
    #pragma unroll
    for (int z = 0; z < KSPL; z++) {
        const float* g = &g_gpart[z][(size_t)b * FOURD];
        float4 a = *(const float4*)&g[j];
        float4 f = *(const float4*)&g[D + j];
        float4 c = *(const float4*)&g[2 * D + j];
        float4 o = *(const float4*)&g[3 * D + j];
        gi.x += a.x; gi.y += a.y; gi.z += a.z; gi.w += a.w;
        gf.x += f.x; gf.y += f.y; gf.z += f.z; gf.w += f.w;
        gg.x += c.x; gg.y += c.y; gg.z += c.z; gg.w += c.w;
        go.x += o.x; go.y += o.y; go.z += o.z; go.w += o.w;
    }
    float4 cold = *(const float4*)&g_c[b * D + j];
    float4 cnew, hnew;
    cnew.x = sigf(gf.x) * cold.x + sigf(gi.x) * tanhf(gg.x);
    cnew.y = sigf(gf.y) * cold.y + sigf(gi.y) * tanhf(gg.y);
    cnew.z = sigf(gf.z) * cold.z + sigf(gi.z) * tanhf(gg.z);
    cnew.w = sigf(gf.w) * cold.w + sigf(gi.w) * tanhf(gg.w);
    hnew.x = sigf(go.x) * tanhf(cnew.x);
    hnew.y = sigf(go.y) * tanhf(cnew.y);
    hnew.z = sigf(go.z) * tanhf(cnew.z);
    hnew.w = sigf(go.w) * tanhf(cnew.w);
    *(float4*)&g_c[b * D + j] = cnew;
    *(float4*)&g_qstar[b * QS + j] = hnew;
    g_q2[b * QS + j + 0] = tf32split(hnew.x);
    g_q2[b * QS + j + 1] = tf32split(hnew.y);
    g_q2[b * QS + j + 2] = tf32split(hnew.z);
    g_q2[b * QS + j + 3] = tf32split(hnew.w);
}

// ---------------- gates GEMM v6: 3xTF32 tensor cores, pre-split float2 operands,
// ----------------  64x64 tile, split-K=2, 3-stage cp.async, conflict-free LDS.64 ----------------
__global__ void __launch_bounds__(256, 2) k_gemm_tc() {
    __shared__ __align__(16) float2 As[3][GBM * SROW];   // 3*64*18*8 = 27648 B
    __shared__ __align__(16) float2 Bs[3][GBN * SROW];   // 27648 B
    int n0 = blockIdx.x * GBN, m0 = blockIdx.y * GBM;
    int kc = blockIdx.z * KCHUNK;
    int t = threadIdx.x;
    int lane = t & 31, wid = t >> 5;
    int warp_m = wid >> 2, warp_n = wid & 3;    // 2 x 4 warp grid
    int g = lane >> 2, tig = lane & 3;

    float acc[2][2][4];
    #pragma unroll
    for (int i = 0; i < 2; i++)
        #pragma unroll
        for (int j = 0; j < 2; j++)
            #pragma unroll
            for (int kq = 0; kq < 4; kq++) acc[i][j][kq] = 0.0f;

    // copy: 512 16B-chunks (2 float2 each) per matrix per stage; thread handles c=t, t+256
    int row0c = t >> 3,          col0c = (t & 7) * 2;          // chunk t
    int row1c = (t + 256) >> 3,  col1c = (t & 7) * 2;          // chunk t+256

    const float2* srcA = g_q2 + (size_t)m0 * QS + kc;
    const float2* srcB = g_W2 + (size_t)n0 * QS + kc;

    #pragma unroll
    for (int s = 0; s < 2; s++) {
        int kof = s * GBK;
        cp_async16(__cvta_generic_to_shared(&As[s][row0c * SROW + col0c]), srcA + (size_t)row0c * QS + kof + col0c);
        cp_async16(__cvta_generic_to_shared(&As[s][row1c * SROW + col1c]), srcA + (size_t)row1c * QS + kof + col1c);
        cp_async16(__cvta_generic_to_shared(&Bs[s][row0c * SROW + col0c]), srcB + (size_t)row0c * QS + kof + col0c);
        cp_async16(__cvta_generic_to_shared(&Bs[s][row1c * SROW + col1c]), srcB + (size_t)row1c * QS + kof + col1c);
        asm volatile("cp.async.commit_group;");
    }

    for (int it = 0; it < GNIT; it++) {
        if (it < GNIT - 1) asm volatile("cp.async.wait_group 1;");
        else               asm volatile("cp.async.wait_group 0;");
        __syncthreads();
        if (it + 2 < GNIT) {
            int st = (it + 2) % 3;
            int kof = (it + 2) * GBK;
            cp_async16(__cvta_generic_to_shared(&As[st][row0c * SROW + col0c]), srcA + (size_t)row0c * QS + kof + col0c);
            cp_async16(__cvta_generic_to_shared(&As[st][row1c * SROW + col1c]), srcA + (size_t)row1c * QS + kof + col1c);
            cp_async16(__cvta_generic_to_shared(&Bs[st][row0c * SROW + col0c]), srcB + (size_t)row0c * QS + kof + col0c);
            cp_async16(__cvta_generic_to_shared(&Bs[st][row1c * SROW + col1c]), srcB + (size_t)row1c * QS + kof + col1c);
            asm volatile("cp.async.commit_group;");
        }
        int cb = it % 3;
        #pragma unroll
        for (int ks = 0; ks < 2; ks++) {
            int kb = ks * 8;
            uint32_t ah[2][4], al[2][4];
            #pragma unroll
            for (int mt = 0; mt < 2; mt++) {
                int mb = warp_m * 32 + mt * 16;
                float2 a0 = As[cb][(mb + g    ) * SROW + kb + tig    ];
                float2 a1 = As[cb][(mb + g + 8) * SROW + kb + tig    ];
                float2 a2 = As[cb][(mb + g    ) * SROW + kb + tig + 4];
                float2 a3 = As[cb][(mb + g + 8) * SROW + kb + tig + 4];
                ah[mt][0] = __float_as_uint(a0.x); al[mt][0] = __float_as_uint(a0.y);
                ah[mt][1] = __float_as_uint(a1.x); al[mt][1] = __float_as_uint(a1.y);
                ah[mt][2] = __float_as_uint(a2.x); al[mt][2] = __float_as_uint(a2.y);
                ah[mt][3] = __float_as_uint(a3.x); al[mt][3] = __float_as_uint(a3.y);
            }
            uint32_t bh[2][2], bl[2][2];
            #pragma unroll
            for (int nt = 0; nt < 2; nt++) {
                int nb = warp_n * 16 + nt * 8;
                float2 b0 = Bs[cb][(nb + g) * SROW + kb + tig    ];
                float2 b1 = Bs[cb][(nb + g) * SROW + kb + tig + 4];
                bh[nt][0] = __float_as_uint(b0.x); bl[nt][0] = __float_as_uint(b0.y);
                bh[nt][1] = __float_as_uint(b1.x); bl[nt][1] = __float_as_uint(b1.y);
            }
            #pragma unroll
            for (int mt = 0; mt < 2; mt++)
                #pragma unroll
                for (int nt = 0; nt < 2; nt++) {
                    mma_tf32(acc[mt][nt], ah[mt], bh[nt]);
                    mma_tf32(acc[mt][nt], ah[mt], bl[nt]);
                    mma_tf32(acc[mt][nt], al[mt], bh[nt]);
                }
        }
    }

    // epilogue: scatter fragments to this split's partial buffer
    float* gp = g_gpart[blockIdx.z];
    #pragma unroll
    for (int mt = 0; mt < 2; mt++) {
        #pragma unroll
        for (int nt = 0; nt < 2; nt++) {
            int row0 = m0 + warp_m * 32 + mt * 16 + g;
            int col  = n0 + warp_n * 16 + nt * 8 + 2 * tig;
            *(float2*)&gp[(size_t)row0 * FOURD + col] =
                make_float2(acc[mt][nt][0], acc[mt][nt][1]);
            *(float2*)&gp[(size_t)(row0 + 8) * FOURD + col] =
                make_float2(acc[mt][nt][2], acc[mt][nt][3]);
        }
    }
}

// ---------------- split segment attention (round-9 proven shape, frozen) ----------------
__global__ void __launch_bounds__(256) k_attn_part(const float* __restrict__ x) {
    __shared__ __align__(16) float q_sh[D];
    __shared__ __align__(16) float rsh[NW][D];
    __shared__ float msh[NW], dsh[NW];

    int b  = blockIdx.x / SPLITS;
    int sp = blockIdx.x % SPLITS;
    int t = threadIdx.x;
    int w = t >> 5, lane = t & 31;

    int segs = g_segoff[b], sege = g_segoff[b + 1];
    int total = sege - segs;
    int start = segs + (int)(((long long)total * sp) / SPLITS);
    int end   = segs + (int)(((long long)total * (sp + 1)) / SPLITS);

    q_sh[t]       = g_qstar[b * QS + t];
    q_sh[t + 256] = g_qstar[b * QS + t + 256];
    __syncthreads();

    float qr[16];
    #pragma unroll
    for (int c = 0; c < 4; c++) {
        float4 qv = *(const float4*)&q_sh[c * 128 + lane * 4];
        qr[c * 4 + 0] = qv.x; qr[c * 4 + 1] = qv.y;
        qr[c * 4 + 2] = qv.z; qr[c * 4 + 3] = qv.w;
    }

    float m = -INFINITY, d = 0.0f;
    float r[16];
    #pragma unroll
    for (int j = 0; j < 16; j++) r[j] = 0.0f;

    int n = start + w;
    float4 xb0, xb1, xb2, xb3;
    if (n < end) {
        const float* p = x + (size_t)n * D;
        xb0 = ((const float4*)(p      ))[lane];
        xb1 = ((const float4*)(p + 128))[lane];
        xb2 = ((const float4*)(p + 256))[lane];
        xb3 = ((const float4*)(p + 384))[lane];
    }
    while (n < end) {
        float4 c0 = xb0, c1 = xb1, c2 = xb2, c3 = xb3;
        int nn = n + NW;
        if (nn < end) {
            const float* p = x + (size_t)nn * D;
            xb0 = ((const float4*)(p      ))[lane];
            xb1 = ((const float4*)(p + 128))[lane];
            xb2 = ((const float4*)(p + 256))[lane];
            xb3 = ((const float4*)(p + 384))[lane];
        }
        float s = c0.x * qr[0]  + c0.y * qr[1]  + c0.z * qr[2]  + c0.w * qr[3]
                + c1.x * qr[4]  + c1.y * qr[5]  + c1.z * qr[6]  + c1.w * qr[7]
                + c2.x * qr[8]  + c2.y * qr[9]  + c2.z * qr[10] + c2.w * qr[11]
                + c3.x * qr[12] + c3.y * qr[13] + c3.z * qr[14] + c3.w * qr[15];
        #pragma unroll
        for (int o = 16; o > 0; o >>= 1) s += __shfl_xor_sync(0xffffffffu, s, o);

        if (s > m) {
            float al = __expf(m - s);   // first iteration: exp(-inf) = 0
            d = d * al + 1.0f;
            r[0]  = r[0]  * al + c0.x;  r[1]  = r[1]  * al + c0.y;
            r[2]  = r[2]  * al + c0.z;  r[3]  = r[3]  * al + c0.w;
            r[4]  = r[4]  * al + c1.x;  r[5]  = r[5]  * al + c1.y;
            r[6]  = r[6]  * al + c1.z;  r[7]  = r[7]  * al + c1.w;
            r[8]  = r[8]  * al + c2.x;  r[9]  = r[9]  * al + c2.y;
            r[10] = r[10] * al + c2.z;  r[11] = r[11] * al + c2.w;
            r[12] = r[12] * al + c3.x;  r[13] = r[13] * al + c3.y;
            r[14] = r[14] * al + c3.z;  r[15] = r[15] * al + c3.w;
            m = s;
        } else {
            float wv = __expf(s - m);
            d += wv;
            r[0]  += wv * c0.x;  r[1]  += wv * c0.y;  r[2]  += wv * c0.z;  r[3]  += wv * c0.w;
            r[4]  += wv * c1.x;  r[5]  += wv * c1.y;  r[6]  += wv * c1.z;  r[7]  += wv * c1.w;
            r[8]  += wv * c2.x;  r[9]  += wv * c2.y;  r[10] += wv * c2.z;  r[11] += wv * c2.w;
            r[12] += wv * c3.x;  r[13] += wv * c3.y;  r[14] += wv * c3.z;  r[15] += wv * c3.w;
        }
        n = nn;
    }

    if (lane == 0) { msh[w] = m; dsh[w] = d; }
    #pragma unroll
    for (int c = 0; c < 4; c++)
        *(float4*)&rsh[w][c * 128 + lane * 4] =
            make_float4(r[c * 4], r[c * 4 + 1], r[c * 4 + 2], r[c * 4 + 3]);
    __syncthreads();

    float M = msh[0];
    #pragma unroll
    for (int p = 1; p < NW; p++) M = fmaxf(M, msh[p]);
    float Mg = isfinite(M) ? M : 0.0f;
    float dd = 0.0f, r0 = 0.0f, r1 = 0.0f;
    #pragma unroll
    for (int p = 0; p < NW; p++) {
        float sc = __expf(msh[p] - Mg);
        dd += dsh[p] * sc;
        r0 += rsh[p][t] * sc;
        r1 += rsh[p][t + 256] * sc;
    }
    int pid = b * SPLITS + sp;
    g_pr[(size_t)pid * D + t]       = r0;
    g_pr[(size_t)pid * D + t + 256] = r1;
    if (t == 0) { g_pm[pid] = M; g_pd[pid] = dd; }
}

// ---------------- combine split partials -> r (plain + split tf32) ----------------
__global__ void k_attn_combine() {
    __shared__ float sm[SPLITS], sd[SPLITS];
    int b = blockIdx.x, t = threadIdx.x;
    if (t < SPLITS) {
        sm[t] = g_pm[b * SPLITS + t];
        sd[t] = g_pd[b * SPLITS + t];
    }
    __syncthreads();
    float M = -INFINITY;
    #pragma unroll
    for (int p = 0; p < SPLITS; p++) M = fmaxf(M, sm[p]);
    if (!isfinite(M)) M = 0.0f;
    float denom = 0.0f;
    float scale[SPLITS];
    #pragma unroll
    for (int p = 0; p < SPLITS; p++) {
        scale[p] = expf(sm[p] - M);
        denom += sd[p] * scale[p];
    }
    float inv = 1.0f / (denom + 1e-16f);
    float r0 = 0.0f, r1 = 0.0f;
    #pragma unroll
    for (int p = 0; p < SPLITS; p++) {
        const float* pr = g_pr + (size_t)(b * SPLITS + p) * D;
        r0 += pr[t]       * scale[p];
        r1 += pr[t + 256] * scale[p];
    }
    r0 *= inv; r1 *= inv;
    g_qstar[b * QS + D + t]       = r0;
    g_qstar[b * QS + D + t + 256] = r1;
    g_q2[b * QS + D + t]          = tf32split(r0);
    g_q2[b * QS + D + t + 256]    = tf32split(r1);
}

// ---------------- projection ----------------
__global__ void k_proj(const float* __restrict__ Wp, const float* __restrict__ bp,
                       float* __restrict__ out) {
    int gw = (blockIdx.x * 256 + threadIdx.x) >> 5;
    int lane = threadIdx.x & 31;
    int bb = gw >> 8, o = gw & 255;
    const float* qr = g_qstar + bb * QS;
    const float* wr = Wp + o * QS;
    float s = 0.0f;
    #pragma unroll
    for (int it = 0; it < QS / 128; it++) {
        int k = lane * 4 + it * 128;
        float4 a = *(const float4*)(qr + k);
        float4 w = *(const float4*)(wr + k);
        s += a.x * w.x + a.y * w.y + a.z * w.z + a.w * w.w;
    }
    #pragma unroll
    for (int off = 16; off > 0; off >>= 1) s += __shfl_xor_sync(0xffffffffu, s, off);
    if (lane == 0) out[gw] = s + bp[o];
}

// ---------------- launch ----------------
extern "C" void kernel_launch(void* const* d_in, const int* in_sizes, int n_in,
                              void* d_out, int out_size) {
    const float* x      = (const float*)d_in[0];
    const void*  batch  = d_in[1];
    const float* W_ih   = (const float*)d_in[2];
    const float* W_hh   = (const float*)d_in[3];
    const float* b_ih   = (const float*)d_in[4];
    const float* b_hh   = (const float*)d_in[5];
    const float* W_proj = (const float*)d_in[6];
    const float* b_proj = (const float*)d_in[7];
    (void)n_in; (void)out_size;
    int N = in_sizes[1];

    int init_blocks = WCOMB_BLKS + STEP0_BLKS + (N + 255) / 256;
    k_init<<<init_blocks, 256>>>(batch, N, W_ih, W_hh, b_ih, b_hh);

    k_attn_part<<<B * SPLITS, 256>>>(x);
    k_attn_combine<<<B, 256>>>();

    for (int s = 1; s < 3; s++) {
        k_gemm_tc<<<dim3(FOURD / GBN, B / GBM, KSPL), 256>>>();
        k_lstm_ew<<<(B * D / 4 + 127) / 128, 128>>>();
        k_attn_part<<<B * SPLITS, 256>>>(x);
        k_attn_combine<<<B, 256>>>();
    }

    k_proj<<<(B * 256) / 8, 256>>>(W_proj, b_proj, (float*)d_out);
}

// round 15
// speedup vs baseline: 1.0298x; 1.0298x over previous
#include <cuda_runtime.h>
#include <math.h>
#include <stdint.h>

#define D      512
#define B      256
#define FOURD  2048
#define QS     1024   // 2*D
#define SPLITS 8
#define NW     8      // warps per attn block (256 threads)
#define NGB    64     // gemm_h blocks inside fused kernel

#define NPARTS 5      // gpart buffers: [0]=h-half, [1..4]=r-half splits

// ---- scratch (no allocations allowed) ----
__device__ float g_WcombT[QS * FOURD];  // [1024][2048] K-major (transposed combined weight)
__device__ float g_bsum[FOURD];
__device__ float g_qstar[B * QS];       // [h | r] row-major (attention/proj consumer)
__device__ float g_qstarT[QS * B];      // [1024][256] K-major (GEMM consumer)
__device__ float g_c[B * D];
__device__ float g_gpart[NPARTS][B * FOURD];
__device__ int   g_segoff[B + 1];
// split-attention partials
__device__ float g_pm[B * SPLITS];
__device__ float g_pd[B * SPLITS];
__device__ float g_pr[B * SPLITS * D];

__device__ __forceinline__ float sigf(float v) { return 1.0f / (1.0f + expf(-v)); }

__device__ __forceinline__ void cp_async16(uint32_t dst_smem, const void* src) {
    asm volatile("cp.async.cg.shared.global [%0], [%1], 16;" :: "r"(dst_smem), "l"(src));
}

// ---------------- fused init: WcombT transpose + bsum + step0 + segscan (round-9) ----------------
#define WT_BLKS  ((FOURD / 32) * (QS / 32))   // 2048
#define STEP0_BLKS (B * D / 256)              // 512
__global__ void k_init(const void* __restrict__ raw, int N,
                       const float* __restrict__ W_ih, const float* __restrict__ W_hh,
                       const float* __restrict__ b_ih, const float* __restrict__ b_hh) {
    __shared__ float s[32][33];
    int blk = blockIdx.x;
    int t = threadIdx.x;
    if (blk < WT_BLKS) {
        int nt = blk >> 5, kt = blk & 31;
        int tx = t & 31, ty = t >> 5;
        #pragma unroll
        for (int i = 0; i < 4; i++) {
            int n = nt * 32 + ty + i * 8;
            int k = kt * 32 + tx;
            float v = W_ih[(size_t)n * QS + k];
            if (k < D) v += W_hh[(size_t)n * D + k];
            s[ty + i * 8][tx] = v;
        }
        __syncthreads();
        #pragma unroll
        for (int i = 0; i < 4; i++) {
            int k = kt * 32 + ty + i * 8;
            int n = nt * 32 + tx;
            g_WcombT[(size_t)k * FOURD + n] = s[tx][ty + i * 8];
        }
        if (blk < 8) g_bsum[blk * 256 + t] = b_ih[blk * 256 + t] + b_hh[blk * 256 + t];
    } else if (blk < WT_BLKS + STEP0_BLKS) {
        int idx = (blk - WT_BLKS) * 256 + t;
        int j = idx & (D - 1);
        float gi = b_ih[j]         + b_hh[j];
        float gg = b_ih[2 * D + j] + b_hh[2 * D + j];
        float go = b_ih[3 * D + j] + b_hh[3 * D + j];
        float c  = sigf(gi) * tanhf(gg);
        float h  = sigf(go) * tanhf(c);
        int b = idx >> 9;
        g_c[idx] = c;
        g_qstar[b * QS + j] = h;
        g_qstarT[j * B + b] = h;
    } else {
        const int* p32 = (const int*)raw;
        bool is64 = (p32[N - 1] == 0) || (p32[N - 2] == 0);
        int i = (blk - WT_BLKS - STEP0_BLKS) * 256 + t;
        if (i >= N) return;
        int cur = is64 ? (int)((const long long*)raw)[i] : p32[i];
        if (i == 0) {
            for (int j = 0; j <= cur; j++) g_segoff[j] = 0;
        } else {
            int prev = is64 ? (int)((const long long*)raw)[i - 1] : p32[i - 1];
            for (int j = prev + 1; j <= cur; j++) g_segoff[j] = i;
        }
        if (i == N - 1) {
            for (int j = cur + 1; j <= B; j++) g_segoff[j] = N;
        }
    }
}

// ---------------- LSTM elementwise, float4 (sums 5 partials + bias) ----------------
__global__ void __launch_bounds__(128) k_lstm_ew() {
    int idx = blockIdx.x * 128 + threadIdx.x;   // over B*D/4
    if (idx >= B * D / 4) return;
    int b = idx >> 7;
    int j = (idx & 127) * 4;
    float4 gi = *(const float4*)&g_bsum[j];
    float4 gf = *(const float4*)&g_bsum[D + j];
    float4 gg = *(const float4*)&g_bsum[2 * D + j];
    float4 go = *(const float4*)&g_bsum[3 * D + j];
    #pragma unroll
    for (int z = 0; z < NPARTS; z++) {
        const float* g = &g_gpart[z][(size_t)b * FOURD];
        float4 a = *(const float4*)&g[j];
        float4 f = *(const float4*)&g[D + j];
        float4 c = *(const float4*)&g[2 * D + j];
        float4 o = *(const float4*)&g[3 * D + j];
        gi.x += a.x; gi.y += a.y; gi.z += a.z; gi.w += a.w;
        gf.x += f.x; gf.y += f.y; gf.z += f.z; gf.w += f.w;
        gg.x += c.x; gg.y += c.y; gg.z += c.z; gg.w += c.w;
        go.x += o.x; go.y += o.y; go.z += o.z; go.w += o.w;
    }
    float4 cold = *(const float4*)&g_c[b * D + j];
    float4 cnew, hnew;
    cnew.x = sigf(gf.x) * cold.x + sigf(gi.x) * tanhf(gg.x);
    cnew.y = sigf(gf.y) * cold.y + sigf(gi.y) * tanhf(gg.y);
    cnew.z = sigf(gf.z) * cold.z + sigf(gi.z) * tanhf(gg.z);
    cnew.w = sigf(gf.w) * cold.w + sigf(gi.w) * tanhf(gg.w);
    hnew.x = sigf(go.x) * tanhf(cnew.x);
    hnew.y = sigf(go.y) * tanhf(cnew.y);
    hnew.z = sigf(go.z) * tanhf(cnew.z);
    hnew.w = sigf(go.w) * tanhf(cnew.w);
    *(float4*)&g_c[b * D + j] = cnew;
    *(float4*)&g_qstar[b * QS + j] = hnew;
    g_qstarT[(j + 0) * B + b] = hnew.x;
    g_qstarT[(j + 1) * B + b] = hnew.y;
    g_qstarT[(j + 2) * B + b] = hnew.z;
    g_qstarT[(j + 3) * B + b] = hnew.w;
}

// ---------------- GEMM tile 64x128, 4x8 microtile f32x2, 3-stage cp.async (low-reg) ----------------
// As: 3 stages of [16][64]; Bs: 3 stages of [16][128]. Computes C[m0+64][n0+128] over kc..kc+16*NIT_.
template<int NIT_>
__device__ __forceinline__ void gemm64x128(float* As, float* Bs, int m0, int n0, int kc, float* gp) {
    int t = threadIdx.x;
    int tx = t & 15, ty = t >> 4;

    unsigned long long acc2[4][4];
    #pragma unroll
    for (int i = 0; i < 4; i++)
        #pragma unroll
        for (int j = 0; j < 4; j++) acc2[i][j] = 0ull;

    int ka = t >> 4, ma = (t & 15) * 4;           // A chunk (1 per thread)
    int kb0 = t >> 5, kb1 = (t + 256) >> 5;        // B chunks (2 per thread)
    int nb = (t & 31) * 4;

    const float* srcA = g_qstarT + (size_t)kc * B + m0;
    const float* srcB = g_WcombT + (size_t)kc * FOURD + n0;

    #pragma unroll
    for (int s = 0; s < 2; s++) {
        int kof = s * 16;
        cp_async16(__cvta_generic_to_shared(As + s * 1024 + ka * 64 + ma),   srcA + (size_t)(kof + ka) * B + ma);
        cp_async16(__cvta_generic_to_shared(Bs + s * 2048 + kb0 * 128 + nb), srcB + (size_t)(kof + kb0) * FOURD + nb);
        cp_async16(__cvta_generic_to_shared(Bs + s * 2048 + kb1 * 128 + nb), srcB + (size_t)(kof + kb1) * FOURD + nb);
        asm volatile("cp.async.commit_group;");
    }

    for (int it = 0; it < NIT_; it++) {
        if (it < NIT_ - 1) asm volatile("cp.async.wait_group 1;");
        else               asm volatile("cp.async.wait_group 0;");
        __syncthreads();
        if (it + 2 < NIT_) {
            int st = (it + 2) % 3;
            int kof = (it + 2) * 16;
            cp_async16(__cvta_generic_to_shared(As + st * 1024 + ka * 64 + ma),   srcA + (size_t)(kof + ka) * B + ma);
            cp_async16(__cvta_generic_to_shared(Bs + st * 2048 + kb0 * 128 + nb), srcB + (size_t)(kof + kb0) * FOURD + nb);
            cp_async16(__cvta_generic_to_shared(Bs + st * 2048 + kb1 * 128 + nb), srcB + (size_t)(kof + kb1) * FOURD + nb);
            asm volatile("cp.async.commit_group;");
        }
        int cb = it % 3;
        #pragma unroll
        for (int kk = 0; kk < 16; kk++) {
            float a[4];
            *(float4*)a = *(const float4*)(As + cb * 1024 + kk * 64 + ty * 4);
            unsigned long long b2[4];
            {
                ulonglong2 bl0 = *(const ulonglong2*)(Bs + cb * 2048 + kk * 128 + tx * 8);
                ulonglong2 bl1 = *(const ulonglong2*)(Bs + cb * 2048 + kk * 128 + tx * 8 + 4);
                b2[0] = bl0.x; b2[1] = bl0.y; b2[2] = bl1.x; b2[3] = bl1.y;
            }
            #pragma unroll
            for (int i = 0; i < 4; i++) {
                unsigned long long a2;
                asm("mov.b64 %0, {%1, %1};" : "=l"(a2) : "r"(__float_as_uint(a[i])));
                #pragma unroll
                for (int j = 0; j < 4; j++)
                    asm("fma.rn.f32x2 %0, %1, %2, %0;"
                        : "+l"(acc2[i][j]) : "l"(a2), "l"(b2[j]));
            }
        }
    }
    #pragma unroll
    for (int i = 0; i < 4; i++) {
        int mrow = m0 + ty * 4 + i;
        unsigned long long* dst = (unsigned long long*)&gp[(size_t)mrow * FOURD + n0 + tx * 8];
        *(ulonglong2*)(dst)     = make_ulonglong2(acc2[i][0], acc2[i][1]);
        *(ulonglong2*)(dst + 2) = make_ulonglong2(acc2[i][2], acc2[i][3]);
    }
}

// ---------------- attention item (round-9 proven body), shared passed in ----------------
__device__ __forceinline__ void attn_item(const float* __restrict__ x, int b, int sp,
                                          float* q_sh, float* rsh, float* msh, float* dsh) {
    int t = threadIdx.x;
    int w = t >> 5, lane = t & 31;

    int segs = g_segoff[b], sege = g_segoff[b + 1];
    int total = sege - segs;
    int start = segs + (int)(((long long)total * sp) / SPLITS);
    int end   = segs + (int)(((long long)total * (sp + 1)) / SPLITS);

    q_sh[t]       = g_qstar[b * QS + t];
    q_sh[t + 256] = g_qstar[b * QS + t + 256];
    __syncthreads();

    float qr[16];
    #pragma unroll
    for (int c = 0; c < 4; c++) {
        float4 qv = *(const float4*)&q_sh[c * 128 + lane * 4];
        qr[c * 4 + 0] = qv.x; qr[c * 4 + 1] = qv.y;
        qr[c * 4 + 2] = qv.z; qr[c * 4 + 3] = qv.w;
    }

    float m = -INFINITY, d = 0.0f;
    float r[16];
    #pragma unroll
    for (int j = 0; j < 16; j++) r[j] = 0.0f;

    int n = start + w;
    float4 xb0, xb1, xb2, xb3;
    if (n < end) {
        const float* p = x + (size_t)n * D;
        xb0 = ((const float4*)(p      ))[lane];
        xb1 = ((const float4*)(p + 128))[lane];
        xb2 = ((const float4*)(p + 256))[lane];
        xb3 = ((const float4*)(p + 384))[lane];
    }
    while (n < end) {
        float4 c0 = xb0, c1 = xb1, c2 = xb2, c3 = xb3;
        int nn = n + NW;
        if (nn < end) {
            const float* p = x + (size_t)nn * D;
            xb0 = ((const float4*)(p      ))[lane];
            xb1 = ((const float4*)(p + 128))[lane];
            xb2 = ((const float4*)(p + 256))[lane];
            xb3 = ((const float4*)(p + 384))[lane];
        }
        float s = c0.x * qr[0]  + c0.y * qr[1]  + c0.z * qr[2]  + c0.w * qr[3]
                + c1.x * qr[4]  + c1.y * qr[5]  + c1.z * qr[6]  + c1.w * qr[7]
                + c2.x * qr[8]  + c2.y * qr[9]  + c2.z * qr[10] + c2.w * qr[11]
                + c3.x * qr[12] + c3.y * qr[13] + c3.z * qr[14] + c3.w * qr[15];
        #pragma unroll
        for (int o = 16; o > 0; o >>= 1) s += __shfl_xor_sync(0xffffffffu, s, o);

        if (s > m) {
            float al = __expf(m - s);   // first iteration: exp(-inf) = 0
            d = d * al + 1.0f;
            r[0]  = r[0]  * al + c0.x;  r[1]  = r[1]  * al + c0.y;
            r[2]  = r[2]  * al + c0.z;  r[3]  = r[3]  * al + c0.w;
            r[4]  = r[4]  * al + c1.x;  r[5]  = r[5]  * al + c1.y;
            r[6]  = r[6]  * al + c1.z;  r[7]  = r[7]  * al + c1.w;
            r[8]  = r[8]  * al + c2.x;  r[9]  = r[9]  * al + c2.y;
            r[10] = r[10] * al + c2.z;  r[11] = r[11] * al + c2.w;
            r[12] = r[12] * al + c3.x;  r[13] = r[13] * al + c3.y;
            r[14] = r[14] * al + c3.z;  r[15] = r[15] * al + c3.w;
            m = s;
        } else {
            float wv = __expf(s - m);
            d += wv;
            r[0]  += wv * c0.x;  r[1]  += wv * c0.y;  r[2]  += wv * c0.z;  r[3]  += wv * c0.w;
            r[4]  += wv * c1.x;  r[5]  += wv * c1.y;  r[6]  += wv * c1.z;  r[7]  += wv * c1.w;
            r[8]  += wv * c2.x;  r[9]  += wv * c2.y;  r[10] += wv * c2.z;  r[11] += wv * c2.w;
            r[12] += wv * c3.x;  r[13] += wv * c3.y;  r[14] += wv * c3.z;  r[15] += wv * c3.w;
        }
        n = nn;
    }

    if (lane == 0) { msh[w] = m; dsh[w] = d; }
    #pragma unroll
    for (int c = 0; c < 4; c++)
        *(float4*)&rsh[w * D + c * 128 + lane * 4] =
            make_float4(r[c * 4], r[c * 4 + 1], r[c * 4 + 2], r[c * 4 + 3]);
    __syncthreads();

    float M = msh[0];
    #pragma unroll
    for (int p = 1; p < NW; p++) M = fmaxf(M, msh[p]);
    float Mg = isfinite(M) ? M : 0.0f;
    float dd = 0.0f, r0 = 0.0f, r1 = 0.0f;
    #pragma unroll
    for (int p = 0; p < NW; p++) {
        float sc = __expf(msh[p] - Mg);
        dd += dsh[p] * sc;
        r0 += rsh[p * D + t] * sc;
        r1 += rsh[p * D + t + 256] * sc;
    }
    int pid = b * SPLITS + sp;
    g_pr[(size_t)pid * D + t]       = r0;
    g_pr[(size_t)pid * D + t + 256] = r1;
    if (t == 0) { g_pm[pid] = M; g_pd[pid] = dd; }
}

// ---------------- fused: gemm_h (blocks 0..63) || attention (blocks 64..) ----------------
__global__ void __launch_bounds__(256) k_fused(const float* __restrict__ x) {
    __shared__ __align__(16) float pool[9216];   // 36KB: gemm As(3072)+Bs(6144); attn q(512)+r(4096)+md(16)
    if (blockIdx.x < NGB) {
        int gy = blockIdx.x & 3;         // m0 tile
        int gx = blockIdx.x >> 2;        // n0 tile
        gemm64x128<32>(pool, pool + 3072, gy * 64, gx * 128, 0, g_gpart[0]);
    } else {
        int bid = blockIdx.x - NGB;
        attn_item(x, bid >> 3, bid & 7, pool, pool + 512, pool + 512 + NW * D, pool + 512 + NW * D + NW);
    }
}

// ---------------- plain attention (last pass, no gemm companion) ----------------
__global__ void __launch_bounds__(256) k_attn(const float* __restrict__ x) {
    __shared__ __align__(16) float pool[512 + NW * D + 2 * NW];
    int bid = blockIdx.x;
    attn_item(x, bid >> 3, bid & 7, pool, pool + 512, pool + 512 + NW * D, pool + 512 + NW * D + NW);
}

// ---------------- gemm_r: r-half (K=512..1023), z-split 4 ----------------
__global__ void __launch_bounds__(256) k_gemm_r() {
    __shared__ __align__(16) float pool[9216];
    gemm64x128<8>(pool, pool + 3072,
                  blockIdx.y * 64, blockIdx.x * 128,
                  512 + blockIdx.z * 128, g_gpart[1 + blockIdx.z]);
}

// ---------------- combine split partials -> r (plain + transposed) ----------------
__global__ void k_attn_combine() {
    __shared__ float sm[SPLITS], sd[SPLITS];
    int b = blockIdx.x, t = threadIdx.x;
    if (t < SPLITS) {
        sm[t] = g_pm[b * SPLITS + t];
        sd[t] = g_pd[b * SPLITS + t];
    }
    __syncthreads();
    float M = -INFINITY;
    #pragma unroll
    for (int p = 0; p < SPLITS; p++) M = fmaxf(M, sm[p]);
    if (!isfinite(M)) M = 0.0f;
    float denom = 0.0f;
    float scale[SPLITS];
    #pragma unroll
    for (int p = 0; p < SPLITS; p++) {
        scale[p] = expf(sm[p] - M);
        denom += sd[p] * scale[p];
    }
    float inv = 1.0f / (denom + 1e-16f);
    float r0 = 0.0f, r1 = 0.0f;
    #pragma unroll
    for (int p = 0; p < SPLITS; p++) {
        const float* pr = g_pr + (size_t)(b * SPLITS + p) * D;
        r0 += pr[t]       * scale[p];
        r1 += pr[t + 256] * scale[p];
    }
    r0 *= inv; r1 *= inv;
    g_qstar[b * QS + D + t]        = r0;
    g_qstar[b * QS + D + t + 256]  = r1;
    g_qstarT[(D + t) * B + b]       = r0;
    g_qstarT[(D + t + 256) * B + b] = r1;
}

// ---------------- projection ----------------
__global__ void k_proj(const float* __restrict__ Wp, const float* __restrict__ bp,
                       float* __restrict__ out) {
    int gw = (blockIdx.x * 256 + threadIdx.x) >> 5;
    int lane = threadIdx.x & 31;
    int bb = gw >> 8, o = gw & 255;
    const float* qr = g_qstar + bb * QS;
    const float* wr = Wp + o * QS;
    float s = 0.0f;
    #pragma unroll
    for (int it = 0; it < QS / 128; it++) {
        int k = lane * 4 + it * 128;
        float4 a = *(const float4*)(qr + k);
        float4 w = *(const float4*)(wr + k);
        s += a.x * w.x + a.y * w.y + a.z * w.z + a.w * w.w;
    }
    #pragma unroll
    for (int off = 16; off > 0; off >>= 1) s += __shfl_xor_sync(0xffffffffu, s, off);
    if (lane == 0) out[gw] = s + bp[o];
}

// ---------------- launch ----------------
extern "C" void kernel_launch(void* const* d_in, const int* in_sizes, int n_in,
                              void* d_out, int out_size) {
    const float* x      = (const float*)d_in[0];
    const void*  batch  = d_in[1];
    const float* W_ih   = (const float*)d_in[2];
    const float* W_hh   = (const float*)d_in[3];
    const float* b_ih   = (const float*)d_in[4];
    const float* b_hh   = (const float*)d_in[5];
    const float* W_proj = (const float*)d_in[6];
    const float* b_proj = (const float*)d_in[7];
    (void)n_in; (void)out_size;
    int N = in_sizes[1];

    int init_blocks = WT_BLKS + STEP0_BLKS + (N + 255) / 256;
    k_init<<<init_blocks, 256>>>(batch, N, W_ih, W_hh, b_ih, b_hh);

    for (int s = 0; s < 2; s++) {
        k_fused<<<NGB + B * SPLITS, 256>>>(x);                 // attn(h_s) || gemm_h(h_s)
        k_attn_combine<<<B, 256>>>();                          // r_s
        k_gemm_r<<<dim3(16, 4, 4), 256>>>();                   // r_s @ W2^T
        k_lstm_ew<<<(B * D / 4 + 127) / 128, 128>>>();         // h_{s+1}
    }
    k_attn<<<B * SPLITS, 256>>>(x);                            // final attention
    k_attn_combine<<<B, 256>>>();

    k_proj<<<(B * 256) / 8, 256>>>(W_proj, b_proj, (float*)d_out);
}

// round 16
// speedup vs baseline: 1.1089x; 1.0768x over previous
#include <cuda_runtime.h>
#include <math.h>
#include <stdint.h>

#define D      512
#define B      256
#define FOURD  2048
#define QS     1024   // 2*D
#define SPLITS 8
#define NW     8      // warps per attn block (256 threads)
#define NGB    128    // gemm_h blocks inside fused kernel (16n x 4m x 2z)

#define NPARTS 10     // gpart: [0..1]=h-half z-splits, [2..9]=r-half z-splits

// ---- scratch (no allocations allowed) ----
__device__ float g_WcombT[QS * FOURD];  // [1024][2048] K-major (transposed combined weight)
__device__ float g_bsum[FOURD];
__device__ float g_qstar[B * QS];       // [h | r] row-major (attention/proj consumer)
__device__ float g_qstarT[QS * B];      // [1024][256] K-major (GEMM consumer)
__device__ float g_c[B * D];
__device__ float g_gpart[NPARTS][B * FOURD];
__device__ int   g_segoff[B + 1];
// split-attention partials
__device__ float g_pm[B * SPLITS];
__device__ float g_pd[B * SPLITS];
__device__ float g_pr[B * SPLITS * D];

__device__ __forceinline__ float sigf(float v) { return 1.0f / (1.0f + expf(-v)); }

__device__ __forceinline__ void cp_async16(uint32_t dst_smem, const void* src) {
    asm volatile("cp.async.cg.shared.global [%0], [%1], 16;" :: "r"(dst_smem), "l"(src));
}

// ---------------- fused init: WcombT transpose + bsum + step0 + segscan ----------------
#define WT_BLKS  ((FOURD / 32) * (QS / 32))   // 2048
#define STEP0_BLKS (B * D / 256)              // 512
__global__ void k_init(const void* __restrict__ raw, int N,
                       const float* __restrict__ W_ih, const float* __restrict__ W_hh,
                       const float* __restrict__ b_ih, const float* __restrict__ b_hh) {
    __shared__ float s[32][33];
    int blk = blockIdx.x;
    int t = threadIdx.x;
    if (blk < WT_BLKS) {
        int nt = blk >> 5, kt = blk & 31;
        int tx = t & 31, ty = t >> 5;
        #pragma unroll
        for (int i = 0; i < 4; i++) {
            int n = nt * 32 + ty + i * 8;
            int k = kt * 32 + tx;
            float v = W_ih[(size_t)n * QS + k];
            if (k < D) v += W_hh[(size_t)n * D + k];
            s[ty + i * 8][tx] = v;
        }
        __syncthreads();
        #pragma unroll
        for (int i = 0; i < 4; i++) {
            int k = kt * 32 + ty + i * 8;
            int n = nt * 32 + tx;
            g_WcombT[(size_t)k * FOURD + n] = s[tx][ty + i * 8];
        }
        if (blk < 8) g_bsum[blk * 256 + t] = b_ih[blk * 256 + t] + b_hh[blk * 256 + t];
    } else if (blk < WT_BLKS + STEP0_BLKS) {
        int idx = (blk - WT_BLKS) * 256 + t;
        int j = idx & (D - 1);
        float gi = b_ih[j]         + b_hh[j];
        float gg = b_ih[2 * D + j] + b_hh[2 * D + j];
        float go = b_ih[3 * D + j] + b_hh[3 * D + j];
        float c  = sigf(gi) * tanhf(gg);
        float h  = sigf(go) * tanhf(c);
        int b = idx >> 9;
        g_c[idx] = c;
        g_qstar[b * QS + j] = h;
        g_qstarT[j * B + b] = h;
    } else {
        const int* p32 = (const int*)raw;
        bool is64 = (p32[N - 1] == 0) || (p32[N - 2] == 0);
        int i = (blk - WT_BLKS - STEP0_BLKS) * 256 + t;
        if (i >= N) return;
        int cur = is64 ? (int)((const long long*)raw)[i] : p32[i];
        if (i == 0) {
            for (int j = 0; j <= cur; j++) g_segoff[j] = 0;
        } else {
            int prev = is64 ? (int)((const long long*)raw)[i - 1] : p32[i - 1];
            for (int j = prev + 1; j <= cur; j++) g_segoff[j] = i;
        }
        if (i == N - 1) {
            for (int j = cur + 1; j <= B; j++) g_segoff[j] = N;
        }
    }
}

// ---------------- LSTM elementwise, float4 (sums 10 partials + bias) ----------------
__global__ void __launch_bounds__(128) k_lstm_ew() {
    int idx = blockIdx.x * 128 + threadIdx.x;   // over B*D/4
    if (idx >= B * D / 4) return;
    int b = idx >> 7;
    int j = (idx & 127) * 4;
    float4 gi = *(const float4*)&g_bsum[j];
    float4 gf = *(const float4*)&g_bsum[D + j];
    float4 gg = *(const float4*)&g_bsum[2 * D + j];
    float4 go = *(const float4*)&g_bsum[3 * D + j];
    #pragma unroll
    for (int z = 0; z < NPARTS; z++) {
        const float* g = &g_gpart[z][(size_t)b * FOURD];
        float4 a = *(const float4*)&g[j];
        float4 f = *(const float4*)&g[D + j];
        float4 c = *(const float4*)&g[2 * D + j];
        float4 o = *(const float4*)&g[3 * D + j];
        gi.x += a.x; gi.y += a.y; gi.z += a.z; gi.w += a.w;
        gf.x += f.x; gf.y += f.y; gf.z += f.z; gf.w += f.w;
        gg.x += c.x; gg.y += c.y; gg.z += c.z; gg.w += c.w;
        go.x += o.x; go.y += o.y; go.z += o.z; go.w += o.w;
    }
    float4 cold = *(const float4*)&g_c[b * D + j];
    float4 cnew, hnew;
    cnew.x = sigf(gf.x) * cold.x + sigf(gi.x) * tanhf(gg.x);
    cnew.y = sigf(gf.y) * cold.y + sigf(gi.y) * tanhf(gg.y);
    cnew.z = sigf(gf.z) * cold.z + sigf(gi.z) * tanhf(gg.z);
    cnew.w = sigf(gf.w) * cold.w + sigf(gi.w) * tanhf(gg.w);
    hnew.x = sigf(go.x) * tanhf(cnew.x);
    hnew.y = sigf(go.y) * tanhf(cnew.y);
    hnew.z = sigf(go.z) * tanhf(cnew.z);
    hnew.w = sigf(go.w) * tanhf(cnew.w);
    *(float4*)&g_c[b * D + j] = cnew;
    *(float4*)&g_qstar[b * QS + j] = hnew;
    g_qstarT[(j + 0) * B + b] = hnew.x;
    g_qstarT[(j + 1) * B + b] = hnew.y;
    g_qstarT[(j + 2) * B + b] = hnew.z;
    g_qstarT[(j + 3) * B + b] = hnew.w;
}

// ---------------- GEMM tile 64x128, 4x8 microtile f32x2, 3-stage cp.async (low-reg, fused use) ----------------
template<int NIT_>
__device__ __forceinline__ void gemm64x128(float* As, float* Bs, int m0, int n0, int kc, float* gp) {
    int t = threadIdx.x;
    int tx = t & 15, ty = t >> 4;

    unsigned long long acc2[4][4];
    #pragma unroll
    for (int i = 0; i < 4; i++)
        #pragma unroll
        for (int j = 0; j < 4; j++) acc2[i][j] = 0ull;

    int ka = t >> 4, ma = (t & 15) * 4;
    int kb0 = t >> 5, kb1 = (t + 256) >> 5;
    int nb = (t & 31) * 4;

    const float* srcA = g_qstarT + (size_t)kc * B + m0;
    const float* srcB = g_WcombT + (size_t)kc * FOURD + n0;

    #pragma unroll
    for (int s = 0; s < 2; s++) {
        int kof = s * 16;
        cp_async16(__cvta_generic_to_shared(As + s * 1024 + ka * 64 + ma),   srcA + (size_t)(kof + ka) * B + ma);
        cp_async16(__cvta_generic_to_shared(Bs + s * 2048 + kb0 * 128 + nb), srcB + (size_t)(kof + kb0) * FOURD + nb);
        cp_async16(__cvta_generic_to_shared(Bs + s * 2048 + kb1 * 128 + nb), srcB + (size_t)(kof + kb1) * FOURD + nb);
        asm volatile("cp.async.commit_group;");
    }

    for (int it = 0; it < NIT_; it++) {
        if (it < NIT_ - 1) asm volatile("cp.async.wait_group 1;");
        else               asm volatile("cp.async.wait_group 0;");
        __syncthreads();
        if (it + 2 < NIT_) {
            int st = (it + 2) % 3;
            int kof = (it + 2) * 16;
            cp_async16(__cvta_generic_to_shared(As + st * 1024 + ka * 64 + ma),   srcA + (size_t)(kof + ka) * B + ma);
            cp_async16(__cvta_generic_to_shared(Bs + st * 2048 + kb0 * 128 + nb), srcB + (size_t)(kof + kb0) * FOURD + nb);
            cp_async16(__cvta_generic_to_shared(Bs + st * 2048 + kb1 * 128 + nb), srcB + (size_t)(kof + kb1) * FOURD + nb);
            asm volatile("cp.async.commit_group;");
        }
        int cb = it % 3;
        #pragma unroll
        for (int kk = 0; kk < 16; kk++) {
            float a[4];
            *(float4*)a = *(const float4*)(As + cb * 1024 + kk * 64 + ty * 4);
            unsigned long long b2[4];
            {
                ulonglong2 bl0 = *(const ulonglong2*)(Bs + cb * 2048 + kk * 128 + tx * 8);
                ulonglong2 bl1 = *(const ulonglong2*)(Bs + cb * 2048 + kk * 128 + tx * 8 + 4);
                b2[0] = bl0.x; b2[1] = bl0.y; b2[2] = bl1.x; b2[3] = bl1.y;
            }
            #pragma unroll
            for (int i = 0; i < 4; i++) {
                unsigned long long a2;
                asm("mov.b64 %0, {%1, %1};" : "=l"(a2) : "r"(__float_as_uint(a[i])));
                #pragma unroll
                for (int j = 0; j < 4; j++)
                    asm("fma.rn.f32x2 %0, %1, %2, %0;"
                        : "+l"(acc2[i][j]) : "l"(a2), "l"(b2[j]));
            }
        }
    }
    #pragma unroll
    for (int i = 0; i < 4; i++) {
        int mrow = m0 + ty * 4 + i;
        unsigned long long* dst = (unsigned long long*)&gp[(size_t)mrow * FOURD + n0 + tx * 8];
        *(ulonglong2*)(dst)     = make_ulonglong2(acc2[i][0], acc2[i][1]);
        *(ulonglong2*)(dst + 2) = make_ulonglong2(acc2[i][2], acc2[i][3]);
    }
}

// ---------------- attention item (round-9 proven body) ----------------
__device__ __forceinline__ void attn_item(const float* __restrict__ x, int b, int sp,
                                          float* q_sh, float* rsh, float* msh, float* dsh) {
    int t = threadIdx.x;
    int w = t >> 5, lane = t & 31;

    int segs = g_segoff[b], sege = g_segoff[b + 1];
    int total = sege - segs;
    int start = segs + (int)(((long long)total * sp) / SPLITS);
    int end   = segs + (int)(((long long)total * (sp + 1)) / SPLITS);

    q_sh[t]       = g_qstar[b * QS + t];
    q_sh[t + 256] = g_qstar[b * QS + t + 256];
    __syncthreads();

    float qr[16];
    #pragma unroll
    for (int c = 0; c < 4; c++) {
        float4 qv = *(const float4*)&q_sh[c * 128 + lane * 4];
        qr[c * 4 + 0] = qv.x; qr[c * 4 + 1] = qv.y;
        qr[c * 4 + 2] = qv.z; qr[c * 4 + 3] = qv.w;
    }

    float m = -INFINITY, d = 0.0f;
    float r[16];
    #pragma unroll
    for (int j = 0; j < 16; j++) r[j] = 0.0f;

    int n = start + w;
    float4 xb0, xb1, xb2, xb3;
    if (n < end) {
        const float* p = x + (size_t)n * D;
        xb0 = ((const float4*)(p      ))[lane];
        xb1 = ((const float4*)(p + 128))[lane];
        xb2 = ((const float4*)(p + 256))[lane];
        xb3 = ((const float4*)(p + 384))[lane];
    }
    while (n < end) {
        float4 c0 = xb0, c1 = xb1, c2 = xb2, c3 = xb3;
        int nn = n + NW;
        if (nn < end) {
            const float* p = x + (size_t)nn * D;
            xb0 = ((const float4*)(p      ))[lane];
            xb1 = ((const float4*)(p + 128))[lane];
            xb2 = ((const float4*)(p + 256))[lane];
            xb3 = ((const float4*)(p + 384))[lane];
        }
        float s = c0.x * qr[0]  + c0.y * qr[1]  + c0.z * qr[2]  + c0.w * qr[3]
                + c1.x * qr[4]  + c1.y * qr[5]  + c1.z * qr[6]  + c1.w * qr[7]
                + c2.x * qr[8]  + c2.y * qr[9]  + c2.z * qr[10] + c2.w * qr[11]
                + c3.x * qr[12] + c3.y * qr[13] + c3.z * qr[14] + c3.w * qr[15];
        #pragma unroll
        for (int o = 16; o > 0; o >>= 1) s += __shfl_xor_sync(0xffffffffu, s, o);

        if (s > m) {
            float al = __expf(m - s);
            d = d * al + 1.0f;
            r[0]  = r[0]  * al + c0.x;  r[1]  = r[1]  * al + c0.y;
            r[2]  = r[2]  * al + c0.z;  r[3]  = r[3]  * al + c0.w;
            r[4]  = r[4]  * al + c1.x;  r[5]  = r[5]  * al + c1.y;
            r[6]  = r[6]  * al + c1.z;  r[7]  = r[7]  * al + c1.w;
            r[8]  = r[8]  * al + c2.x;  r[9]  = r[9]  * al + c2.y;
            r[10] = r[10] * al + c2.z;  r[11] = r[11] * al + c2.w;
            r[12] = r[12] * al + c3.x;  r[13] = r[13] * al + c3.y;
            r[14] = r[14] * al + c3.z;  r[15] = r[15] * al + c3.w;
            m = s;
        } else {
            float wv = __expf(s - m);
            d += wv;
            r[0]  += wv * c0.x;  r[1]  += wv * c0.y;  r[2]  += wv * c0.z;  r[3]  += wv * c0.w;
            r[4]  += wv * c1.x;  r[5]  += wv * c1.y;  r[6]  += wv * c1.z;  r[7]  += wv * c1.w;
            r[8]  += wv * c2.x;  r[9]  += wv * c2.y;  r[10] += wv * c2.z;  r[11] += wv * c2.w;
            r[12] += wv * c3.x;  r[13] += wv * c3.y;  r[14] += wv * c3.z;  r[15] += wv * c3.w;
        }
        n = nn;
    }

    if (lane == 0) { msh[w] = m; dsh[w] = d; }
    #pragma unroll
    for (int c = 0; c < 4; c++)
        *(float4*)&rsh[w * D + c * 128 + lane * 4] =
            make_float4(r[c * 4], r[c * 4 + 1], r[c * 4 + 2], r[c * 4 + 3]);
    __syncthreads();

    float M = msh[0];
    #pragma unroll
    for (int p = 1; p < NW; p++) M = fmaxf(M, msh[p]);
    float Mg = isfinite(M) ? M : 0.0f;
    float dd = 0.0f, r0 = 0.0f, r1 = 0.0f;
    #pragma unroll
    for (int p = 0; p < NW; p++) {
        float sc = __expf(msh[p] - Mg);
        dd += dsh[p] * sc;
        r0 += rsh[p * D + t] * sc;
        r1 += rsh[p * D + t + 256] * sc;
    }
    int pid = b * SPLITS + sp;
    g_pr[(size_t)pid * D + t]       = r0;
    g_pr[(size_t)pid * D + t + 256] = r1;
    if (t == 0) { g_pm[pid] = M; g_pd[pid] = dd; }
}

// ---------------- fused: gemm_h z-split 2 (blocks 0..127) || attention (blocks 128..) ----------------
__global__ void __launch_bounds__(256) k_fused(const float* __restrict__ x) {
    __shared__ __align__(16) float pool[9216];   // 36KB
    if (blockIdx.x < NGB) {
        int bz = blockIdx.x & 1;          // K half within h-range
        int gm = (blockIdx.x >> 1) & 3;   // m tile (4 x 64)
        int gn = blockIdx.x >> 3;         // n tile (16 x 128)
        gemm64x128<16>(pool, pool + 3072, gm * 64, gn * 128, bz * 256, g_gpart[bz]);
    } else {
        int bid = blockIdx.x - NGB;
        attn_item(x, bid >> 3, bid & 7, pool, pool + 512, pool + 512 + NW * D, pool + 512 + NW * D + NW);
    }
}

// ---------------- plain attention (last pass) ----------------
__global__ void __launch_bounds__(256) k_attn(const float* __restrict__ x) {
    __shared__ __align__(16) float pool[512 + NW * D + 2 * NW];
    int bid = blockIdx.x;
    attn_item(x, bid >> 3, bid & 7, pool, pool + 512, pool + 512 + NW * D, pool + 512 + NW * D + NW);
}

// ---------------- gemm_r: round-9 128x128/8x8 body, K=512..1023, z-split 8 ----------------
#define RBM 128
#define RBN 128
#define RBK 16
#define RNIT 4        // KCH = 64
__global__ void __launch_bounds__(256, 2) k_gemm_r() {
    __shared__ __align__(16) float As[3][RBK][RBM];
    __shared__ __align__(16) float Bs[3][RBK][RBN];
    int n0 = blockIdx.x * RBN, m0 = blockIdx.y * RBM;
    int kc = 512 + blockIdx.z * 64;
    int t = threadIdx.x;
    int tx = t & 15, ty = t >> 4;

    unsigned long long acc2[8][4];
    #pragma unroll
    for (int i = 0; i < 8; i++)
        #pragma unroll
        for (int j = 0; j < 4; j++) acc2[i][j] = 0ull;

    int kr0 = t >> 5, kr1 = kr0 + 8;
    int mq  = (t & 31) * 4;

    const float* srcA = g_qstarT + (size_t)kc * B;
    const float* srcB = g_WcombT + (size_t)kc * FOURD;

    #pragma unroll
    for (int s = 0; s < 2; s++) {
        int kof = s * RBK;
        cp_async16(__cvta_generic_to_shared(&As[s][kr0][mq]), srcA + (size_t)(kof + kr0) * B + m0 + mq);
        cp_async16(__cvta_generic_to_shared(&As[s][kr1][mq]), srcA + (size_t)(kof + kr1) * B + m0 + mq);
        cp_async16(__cvta_generic_to_shared(&Bs[s][kr0][mq]), srcB + (size_t)(kof + kr0) * FOURD + n0 + mq);
        cp_async16(__cvta_generic_to_shared(&Bs[s][kr1][mq]), srcB + (size_t)(kof + kr1) * FOURD + n0 + mq);
        asm volatile("cp.async.commit_group;");
    }

    #pragma unroll
    for (int it = 0; it < RNIT; it++) {
        if (it < RNIT - 1) asm volatile("cp.async.wait_group 1;");
        else               asm volatile("cp.async.wait_group 0;");
        __syncthreads();
        if (it + 2 < RNIT) {
            int st = (it + 2) % 3;
            int kof = (it + 2) * RBK;
            cp_async16(__cvta_generic_to_shared(&As[st][kr0][mq]), srcA + (size_t)(kof + kr0) * B + m0 + mq);
            cp_async16(__cvta_generic_to_shared(&As[st][kr1][mq]), srcA + (size_t)(kof + kr1) * B + m0 + mq);
            cp_async16(__cvta_generic_to_shared(&Bs[st][kr0][mq]), srcB + (size_t)(kof + kr0) * FOURD + n0 + mq);
            cp_async16(__cvta_generic_to_shared(&Bs[st][kr1][mq]), srcB + (size_t)(kof + kr1) * FOURD + n0 + mq);
            asm volatile("cp.async.commit_group;");
        }
        int cb = it % 3;
        #pragma unroll
        for (int kk = 0; kk < RBK; kk++) {
            float a[8];
            *(float4*)(a)     = *(const float4*)&As[cb][kk][ty * 8];
            *(float4*)(a + 4) = *(const float4*)&As[cb][kk][ty * 8 + 4];
            unsigned long long b2[4];
            {
                ulonglong2 bl0 = *(const ulonglong2*)&Bs[cb][kk][tx * 8];
                ulonglong2 bl1 = *(const ulonglong2*)&Bs[cb][kk][tx * 8 + 4];
                b2[0] = bl0.x; b2[1] = bl0.y; b2[2] = bl1.x; b2[3] = bl1.y;
            }
            #pragma unroll
            for (int i = 0; i < 8; i++) {
                unsigned long long a2;
                asm("mov.b64 %0, {%1, %1};" : "=l"(a2) : "r"(__float_as_uint(a[i])));
                #pragma unroll
                for (int j = 0; j < 4; j++)
                    asm("fma.rn.f32x2 %0, %1, %2, %0;"
                        : "+l"(acc2[i][j]) : "l"(a2), "l"(b2[j]));
            }
        }
    }
    float* gp = g_gpart[2 + blockIdx.z];
    #pragma unroll
    for (int i = 0; i < 8; i++) {
        int mrow = m0 + ty * 8 + i;
        unsigned long long* dst = (unsigned long long*)&gp[(size_t)mrow * FOURD + n0 + tx * 8];
        *(ulonglong2*)(dst)     = make_ulonglong2(acc2[i][0], acc2[i][1]);
        *(ulonglong2*)(dst + 2) = make_ulonglong2(acc2[i][2], acc2[i][3]);
    }
}

// ---------------- combine split partials -> r (plain + transposed) ----------------
__global__ void k_attn_combine() {
    __shared__ float sm[SPLITS], sd[SPLITS];
    int b = blockIdx.x, t = threadIdx.x;
    if (t < SPLITS) {
        sm[t] = g_pm[b * SPLITS + t];
        sd[t] = g_pd[b * SPLITS + t];
    }
    __syncthreads();
    float M = -INFINITY;
    #pragma unroll
    for (int p = 0; p < SPLITS; p++) M = fmaxf(M, sm[p]);
    if (!isfinite(M)) M = 0.0f;
    float denom = 0.0f;
    float scale[SPLITS];
    #pragma unroll
    for (int p = 0; p < SPLITS; p++) {
        scale[p] = expf(sm[p] - M);
        denom += sd[p] * scale[p];
    }
    float inv = 1.0f / (denom + 1e-16f);
    float r0 = 0.0f, r1 = 0.0f;
    #pragma unroll
    for (int p = 0; p < SPLITS; p++) {
        const float* pr = g_pr + (size_t)(b * SPLITS + p) * D;
        r0 += pr[t]       * scale[p];
        r1 += pr[t + 256] * scale[p];
    }
    r0 *= inv; r1 *= inv;
    g_qstar[b * QS + D + t]        = r0;
    g_qstar[b * QS + D + t + 256]  = r1;
    g_qstarT[(D + t) * B + b]       = r0;
    g_qstarT[(D + t + 256) * B + b] = r1;
}

// ---------------- projection ----------------
__global__ void k_proj(const float* __restrict__ Wp, const float* __restrict__ bp,
                       float* __restrict__ out) {
    int gw = (blockIdx.x * 256 + threadIdx.x) >> 5;
    int lane = threadIdx.x & 31;
    int bb = gw >> 8, o = gw & 255;
    const float* qr = g_qstar + bb * QS;
    const float* wr = Wp + o * QS;
    float s = 0.0f;
    #pragma unroll
    for (int it = 0; it < QS / 128; it++) {
        int k = lane * 4 + it * 128;
        float4 a = *(const float4*)(qr + k);
        float4 w = *(const float4*)(wr + k);
        s += a.x * w.x + a.y * w.y + a.z * w.z + a.w * w.w;
    }
    #pragma unroll
    for (int off = 16; off > 0; off >>= 1) s += __shfl_xor_sync(0xffffffffu, s, off);
    if (lane == 0) out[gw] = s + bp[o];
}

// ---------------- launch ----------------
extern "C" void kernel_launch(void* const* d_in, const int* in_sizes, int n_in,
                              void* d_out, int out_size) {
    const float* x      = (const float*)d_in[0];
    const void*  batch  = d_in[1];
    const float* W_ih   = (const float*)d_in[2];
    const float* W_hh   = (const float*)d_in[3];
    const float* b_ih   = (const float*)d_in[4];
    const float* b_hh   = (const float*)d_in[5];
    const float* W_proj = (const float*)d_in[6];
    const float* b_proj = (const float*)d_in[7];
    (void)n_in; (void)out_size;
    int N = in_sizes[1];

    int init_blocks = WT_BLKS + STEP0_BLKS + (N + 255) / 256;
    k_init<<<init_blocks, 256>>>(batch, N, W_ih, W_hh, b_ih, b_hh);

    for (int s = 0; s < 2; s++) {
        k_fused<<<NGB + B * SPLITS, 256>>>(x);                 // attn(h_s) || gemm_h(h_s)
        k_attn_combine<<<B, 256>>>();                          // r_s
        k_gemm_r<<<dim3(16, 2, 8), 256>>>();                   // r_s @ W2^T
        k_lstm_ew<<<(B * D / 4 + 127) / 128, 128>>>();         // h_{s+1}
    }
    k_attn<<<B * SPLITS, 256>>>(x);                            // final attention
    k_attn_combine<<<B, 256>>>();

    k_proj<<<(B * 256) / 8, 256>>>(W_proj, b_proj, (float*)d_out);
}